// round 8
// baseline (speedup 1.0000x reference)
#include <cuda_runtime.h>
#include <stdint.h>

// GraphRewiring: transitive closure of body-edge adjacency (attr==0),
// emit shortcut edges (closure & ~adj) appended to original edge list.
//
// R8: SCC warm-start (R7 algorithm) fused back into 2 launches:
//   init  : zero barrier slots / flags / pivot, detect int64-vs-int32
//   fused : P0 zero adj/radj -> P1 build(+copy originals, pivot=atomicMax)
//           -> P2 blocks 0,1: fwd/bwd BFS (F, B); blocks 2..: PRE-WRITE the
//              all-shortcut output pattern (hidden in BFS shadow)
//           -> P3 seed R[i] = adj | (i in B ? F|{p}), expanded = F&B
//           -> P4 frontier expansion to fixpoint (tiny residual work)
//           -> P5 emit fix-up: only words with sc != 0xFFFFFFFF
//
// Output layout (float32, out_size = 3*(E+N*N)):
//   [0, E)               : edge_index[0] (src) as float
//   [E, E+NN)            : new_src
//   [E+NN, 2E+NN)        : edge_index[1] (dst) as float
//   [2E+NN, 2E+2NN)      : new_dst
//   [2(E+NN), 2(E+NN)+E) : edge_attr copy
//   [2(E+NN)+E, 3(E+NN)) : new_attr (3.0 if shortcut else -1.0)

#define N_NODES 1024
#define NW 32
#define FULLMASK 0xFFFFFFFFu
#define GRID 128
#define TPB 256
#define MAX_ITERS 8
#define NBAR 16

static __device__ uint32_t g_adj[N_NODES * NW];
static __device__ uint32_t g_radj[N_NODES * NW];
static __device__ uint32_t g_R[N_NODES * NW];
static __device__ uint32_t g_F[NW];
static __device__ uint32_t g_B[NW];
static __device__ int g_pivot;
static __device__ int g_i64flag;
static __device__ int g_bar[NBAR];
static __device__ int g_changed[MAX_ITERS];

// ---------------------------------------------------------------------------
// init: zero per-replay sync state, detect dtype. (Runs inside the graph, so
// every replay re-zeros barriers/flags.)
__global__ void init_kernel(const int* __restrict__ ei32) {
    int t = threadIdx.x;
    if (t < NBAR) g_bar[t] = 0;
    if (t < MAX_ITERS) g_changed[t] = 0;
    if (t == 0) {
        g_pivot = 0;
        // int64 little-endian with node ids < 1024 => every odd word is 0.
        int allzero = 1;
        for (int k = 0; k < 64; k++)
            if (ei32[2 * k + 1] != 0) { allzero = 0; break; }
        g_i64flag = allzero;
    }
}

// ---------------------------------------------------------------------------
// Grid barrier + optional flag exchange. 128 blocks x 256 threads at
// 1 block/SM (launch_bounds) on 148 SMs => all co-resident, spin is
// deadlock-free. Release fence before arrive; acquire fence after spin.
__device__ __forceinline__ int grid_sync_flag(int slot, int it,
                                              int* s_changed, int* s_flag) {
    __syncthreads();
    if (threadIdx.x == 0) {
        if (it >= 0 && *s_changed) g_changed[it] = 1;
        *s_changed = 0;
        __threadfence();
        atomicAdd(&g_bar[slot], 1);
        while (*(volatile int*)&g_bar[slot] < GRID) __nanosleep(32);
        __threadfence();
        *s_flag = (it >= 0) ? __ldcg(&g_changed[it]) : 1;
    }
    __syncthreads();
    return *s_flag;
}

// ---------------------------------------------------------------------------
// Emit one 32-slot word (all three segments). Used by prewrite (sc=FULL) and
// by the post-closure fix-up, so both produce byte-identical data.
__device__ __forceinline__ void emit_word(float* __restrict__ out, int E,
                                          int w, uint32_t sc) {
    const int NN = N_NODES * N_NODES;
    int p_base = w << 5;
    int j0 = (w & 31) << 5;
    float fi = (float)(w >> 5);

    float* so = out + E + p_base;                   // new_src
    float* dd = out + (E + NN) + E + p_base;        // new_dst
    float* ao = out + 2 * (E + NN) + E + p_base;    // new_attr

    #pragma unroll
    for (int q = 0; q < 32; q += 4) {
        bool b0 = (sc >> (q + 0)) & 1u;
        bool b1 = (sc >> (q + 1)) & 1u;
        bool b2 = (sc >> (q + 2)) & 1u;
        bool b3 = (sc >> (q + 3)) & 1u;
        float4 s4 = make_float4(b0 ? fi : 0.f, b1 ? fi : 0.f,
                                b2 ? fi : 0.f, b3 ? fi : 0.f);
        float4 d4 = make_float4(b0 ? (float)(j0 + q + 0) : 0.f,
                                b1 ? (float)(j0 + q + 1) : 0.f,
                                b2 ? (float)(j0 + q + 2) : 0.f,
                                b3 ? (float)(j0 + q + 3) : 0.f);
        float4 a4 = make_float4(b0 ? 3.f : -1.f, b1 ? 3.f : -1.f,
                                b2 ? 3.f : -1.f, b3 ? 3.f : -1.f);
        *(float4*)(so + q) = s4;
        *(float4*)(dd + q) = d4;
        *(float4*)(ao + q) = a4;
    }
}

// ---------------------------------------------------------------------------
__global__ void __launch_bounds__(TPB, 1)
fused_kernel(const int* __restrict__ ei32, const float* __restrict__ attr,
             float* __restrict__ out, int E) {
    __shared__ int s_changed, s_flag;
    __shared__ uint32_t sR[NW], sExp[NW], sFr[NW];
    __shared__ int sAny;

    const int tid  = blockIdx.x * TPB + threadIdx.x;   // 0..32767
    const int lane = threadIdx.x & 31;
    const int wid  = threadIdx.x >> 5;                 // 0..7
    const int row  = tid >> 5;                         // 0..1023 (warp == row)
    const int NN   = N_NODES * N_NODES;
    int bar = 0;

    if (threadIdx.x == 0) { s_changed = 0; s_flag = 1; }

    // ---- P0: zero adjacency bitsets (1 word per array per thread) ----------
    g_adj[tid] = 0u;
    g_radj[tid] = 0u;
    grid_sync_flag(bar++, -1, &s_changed, &s_flag);

    const int i64 = g_i64flag;

    // ---- P1: copy originals + scatter adj/radj + pivot ---------------------
    for (int e = tid; e < E; e += GRID * TPB) {
        int src, dst;
        if (i64) { src = ei32[2 * e]; dst = ei32[2 * (E + e)]; }
        else     { src = ei32[e];     dst = ei32[E + e]; }
        float a = attr[e];
        out[e] = (float)src;
        out[(E + NN) + e] = (float)dst;
        out[2 * (E + NN) + e] = a;
        if (a == 0.0f) {
            atomicOr(&g_adj[src * NW + (dst >> 5)], 1u << (dst & 31));
            atomicOr(&g_radj[dst * NW + (src >> 5)], 1u << (src & 31));
            atomicMax(&g_pivot, dst);           // deterministic: max body dst
        }
    }
    grid_sync_flag(bar++, -1, &s_changed, &s_flag);

    // ---- P2: blocks 0,1 = BFS (F fwd / B bwd); blocks 2.. = prewrite -------
    if (blockIdx.x <= 1) {
        const uint32_t* Adj = (blockIdx.x == 0) ? g_adj : g_radj;
        const int p = g_pivot;
        if (threadIdx.x < NW) { sR[threadIdx.x] = Adj[p * NW + threadIdx.x];
                                sExp[threadIdx.x] = 0u; }
        __syncthreads();
        for (int level = 0; level < N_NODES + 1; level++) {
            if (threadIdx.x == 0) sAny = 0;
            __syncthreads();
            if (threadIdx.x < NW) {
                sFr[threadIdx.x] = sR[threadIdx.x] & ~sExp[threadIdx.x];
                sExp[threadIdx.x] = sR[threadIdx.x];
                if (sFr[threadIdx.x]) sAny = 1;   // benign race, all write 1
            }
            __syncthreads();
            if (!sAny) break;
            uint32_t accum = 0;
            #pragma unroll 1
            for (int ww = wid; ww < NW; ww += 8) {   // 8 warps, 4 words each
                uint32_t bits = sFr[ww];             // warp-uniform
                const uint32_t* pk = &Adj[(ww << 10) + lane];
                while (bits) {
                    int j0 = __ffs(bits) - 1; bits &= bits - 1;
                    int j1 = j0, j2 = j0, j3 = j0;
                    int j4 = j0, j5 = j0, j6 = j0, j7 = j0;
                    if (bits) { j1 = __ffs(bits) - 1; bits &= bits - 1; }
                    if (bits) { j2 = __ffs(bits) - 1; bits &= bits - 1; }
                    if (bits) { j3 = __ffs(bits) - 1; bits &= bits - 1; }
                    if (bits) { j4 = __ffs(bits) - 1; bits &= bits - 1; }
                    if (bits) { j5 = __ffs(bits) - 1; bits &= bits - 1; }
                    if (bits) { j6 = __ffs(bits) - 1; bits &= bits - 1; }
                    if (bits) { j7 = __ffs(bits) - 1; bits &= bits - 1; }
                    uint32_t v0 = pk[j0 << 5];
                    uint32_t v1 = pk[j1 << 5];
                    uint32_t v2 = pk[j2 << 5];
                    uint32_t v3 = pk[j3 << 5];
                    uint32_t v4 = pk[j4 << 5];
                    uint32_t v5 = pk[j5 << 5];
                    uint32_t v6 = pk[j6 << 5];
                    uint32_t v7 = pk[j7 << 5];
                    accum |= (v0 | v1) | (v2 | v3) | (v4 | v5) | (v6 | v7);
                }
            }
            if (accum) atomicOr(&sR[lane], accum);
            __syncthreads();
        }
        if (threadIdx.x < NW) {
            if (blockIdx.x == 0) g_F[threadIdx.x] = sR[threadIdx.x];
            else                 g_B[threadIdx.x] = sR[threadIdx.x];
        }
    } else {
        // Prewrite the dense "all shortcut" pattern, hidden in BFS's shadow.
        int t2 = (blockIdx.x - 2) * TPB + threadIdx.x;
        for (int w = t2; w < N_NODES * NW; w += (GRID - 2) * TPB)
            emit_word(out, E, w, FULLMASK);
    }
    grid_sync_flag(bar++, -1, &s_changed, &s_flag);

    // ---- P3: seed rows with warm start -------------------------------------
    const int p = g_pivot;
    const uint32_t Fl = g_F[lane];
    const uint32_t Bl = g_B[lane];
    const int inB = (g_B[row >> 5] >> (row & 31)) & 1;

    uint32_t rowreg = g_adj[(row << 5) + lane];
    uint32_t expanded = 0;
    if (inB) {
        // closure(row) >= F u {p}; closure(k) == F exactly for k in F&B.
        rowreg |= Fl;
        if (lane == (p >> 5)) rowreg |= 1u << (p & 31);
        expanded = Fl & Bl;
    }
    g_R[(row << 5) + lane] = rowreg;
    grid_sync_flag(bar++, -1, &s_changed, &s_flag);

    // ---- P4: frontier expansion to fixpoint (tiny residual) ----------------
    for (int it = 0; it < MAX_ITERS; it++) {
        uint32_t delta = rowreg & ~expanded;
        uint32_t acc = rowreg;

        if (__any_sync(FULLMASK, delta != 0u)) {
            #pragma unroll 1
            for (int kw = 0; kw < NW; kw++) {
                uint32_t bits = __shfl_sync(FULLMASK, delta, kw);
                if (!bits) continue;
                const uint32_t* pk = &g_R[(kw << 10) + lane];
                while (bits) {
                    int j0 = __ffs(bits) - 1; bits &= bits - 1;
                    int j1 = j0, j2 = j0, j3 = j0;
                    int j4 = j0, j5 = j0, j6 = j0, j7 = j0;
                    if (bits) { j1 = __ffs(bits) - 1; bits &= bits - 1; }
                    if (bits) { j2 = __ffs(bits) - 1; bits &= bits - 1; }
                    if (bits) { j3 = __ffs(bits) - 1; bits &= bits - 1; }
                    if (bits) { j4 = __ffs(bits) - 1; bits &= bits - 1; }
                    if (bits) { j5 = __ffs(bits) - 1; bits &= bits - 1; }
                    if (bits) { j6 = __ffs(bits) - 1; bits &= bits - 1; }
                    if (bits) { j7 = __ffs(bits) - 1; bits &= bits - 1; }
                    uint32_t v0 = pk[j0 << 5];
                    uint32_t v1 = pk[j1 << 5];
                    uint32_t v2 = pk[j2 << 5];
                    uint32_t v3 = pk[j3 << 5];
                    uint32_t v4 = pk[j4 << 5];
                    uint32_t v5 = pk[j5 << 5];
                    uint32_t v6 = pk[j6 << 5];
                    uint32_t v7 = pk[j7 << 5];
                    acc |= (v0 | v1) | (v2 | v3) | (v4 | v5) | (v6 | v7);
                }
            }
        }

        expanded = rowreg;
        uint32_t newbits = acc & ~rowreg;
        if (__any_sync(FULLMASK, newbits != 0u)) {
            if (newbits) atomicOr(&g_R[(row << 5) + lane], newbits);
            if (lane == 0) s_changed = 1;
        }
        int flag = grid_sync_flag(bar++, it, &s_changed, &s_flag);
        rowreg = __ldcg(&g_R[(row << 5) + lane]);
        if (flag == 0) break;
    }

    // ---- P5: emit fix-up (only words that differ from prewrite) ------------
    {
        int w = tid;                                // exactly 32768 threads
        uint32_t sc = g_R[w] & ~g_adj[w];
        if (sc != FULLMASK) emit_word(out, E, w, sc);
    }
}

// ---------------------------------------------------------------------------
extern "C" void kernel_launch(void* const* d_in, const int* in_sizes, int n_in,
                              void* d_out, int out_size) {
    const int* ei = (const int*)d_in[0];
    const float* attr = (const float*)d_in[1];
    float* out = (float*)d_out;
    int E = in_sizes[1];

    init_kernel<<<1, 64>>>(ei);
    fused_kernel<<<GRID, TPB>>>(ei, attr, out, E);
}

// round 9
// speedup vs baseline: 1.2560x; 1.2560x over previous
#include <cuda_runtime.h>
#include <stdint.h>

// GraphRewiring: transitive closure of body-edge adjacency (attr==0),
// emit shortcut edges (closure & ~adj) appended to original edge list.
//
// R9: barrier-latency attack.
//   - pure-poll grid barrier (no __nanosleep; wakeup ~1 L2 round trip)
//   - barrier count 7 -> ~4: zeroing moved to init launch; seed + first
//     expansion merged via the analytic seed formula
//       seed(k) = adj[k] | (k in B ? F u {p} : 0)
//   - 1 warp per row (plain stores, no atomicOr merge, no row reload)
//   - pivot via warp reduce_max + 1 atomic/warp
//   - TPB=512: BFS uses 16 warps; prewrite/fixup use 64K threads
//
// Output layout (float32, out_size = 3*(E+N*N)):
//   [0, E)               : edge_index[0] (src) as float
//   [E, E+NN)            : new_src
//   [E+NN, 2E+NN)        : edge_index[1] (dst) as float
//   [2E+NN, 2E+2NN)      : new_dst
//   [2(E+NN), 2(E+NN)+E) : edge_attr copy
//   [2(E+NN)+E, 3(E+NN)) : new_attr (3.0 if shortcut else -1.0)

#define N_NODES 1024
#define NW 32
#define FULLMASK 0xFFFFFFFFu
#define GRID 128
#define TPB 512
#define MAX_ITERS 8
#define NBAR 16

static __device__ uint32_t g_adj[N_NODES * NW];
static __device__ uint32_t g_radj[N_NODES * NW];
static __device__ uint32_t g_R[N_NODES * NW];
static __device__ uint32_t g_F[NW];
static __device__ uint32_t g_B[NW];
static __device__ int g_pivot;
static __device__ int g_i64flag;
static __device__ int g_bar[NBAR];
static __device__ int g_changed[MAX_ITERS];

// ---------------------------------------------------------------------------
// init: zero adjacency scratch + per-replay sync state, detect dtype.
// Separate launch => the graph edge orders it before fused_kernel (free
// "barrier"). 64 blocks x 512 threads.
__global__ void init_kernel(const int* __restrict__ ei32) {
    int t = blockIdx.x * blockDim.x + threadIdx.x;   // 0..32767
    g_adj[t] = 0u;
    g_radj[t] = 0u;
    if (t < NBAR) g_bar[t] = 0;
    if (t < MAX_ITERS) g_changed[t] = 0;
    if (t == 0) {
        g_pivot = 0;
        // int64 little-endian with node ids < 1024 => every odd word is 0.
        int allzero = 1;
        for (int k = 0; k < 64; k++)
            if (ei32[2 * k + 1] != 0) { allzero = 0; break; }
        g_i64flag = allzero;
    }
}

// ---------------------------------------------------------------------------
// Grid barrier + optional flag exchange. 128 blocks x 512 threads at
// 1 block/SM (launch_bounds) on 148 SMs => all co-resident, spin is
// deadlock-free. Pure poll (no nanosleep): release latency ~1 L2 round trip.
__device__ __forceinline__ int grid_sync_flag(int slot, int it,
                                              int* s_changed, int* s_flag) {
    __syncthreads();
    if (threadIdx.x == 0) {
        if (it >= 0 && *s_changed) g_changed[it] = 1;
        *s_changed = 0;
        __threadfence();
        atomicAdd(&g_bar[slot], 1);
        while (*(volatile int*)&g_bar[slot] < GRID) { }
        __threadfence();
        *s_flag = (it >= 0) ? __ldcg(&g_changed[it]) : 1;
    }
    __syncthreads();
    return *s_flag;
}

// ---------------------------------------------------------------------------
// Emit 16 output slots (half a 32-slot word) across all three segments.
// Prewrite uses sc16=0xFFFF; fix-up recomputes the same formula, so both
// produce byte-identical data for unchanged halves.
__device__ __forceinline__ void emit_half(float* __restrict__ out, int E,
                                          int w, int half, uint32_t sc16) {
    const int NN = N_NODES * N_NODES;
    int p_base = (w << 5) + (half << 4);
    int j0 = ((w & 31) << 5) + (half << 4);
    float fi = (float)(w >> 5);

    float* so = out + E + p_base;                   // new_src
    float* dd = out + (E + NN) + E + p_base;        // new_dst
    float* ao = out + 2 * (E + NN) + E + p_base;    // new_attr

    #pragma unroll
    for (int q = 0; q < 16; q += 4) {
        bool b0 = (sc16 >> (q + 0)) & 1u;
        bool b1 = (sc16 >> (q + 1)) & 1u;
        bool b2 = (sc16 >> (q + 2)) & 1u;
        bool b3 = (sc16 >> (q + 3)) & 1u;
        float4 s4 = make_float4(b0 ? fi : 0.f, b1 ? fi : 0.f,
                                b2 ? fi : 0.f, b3 ? fi : 0.f);
        float4 d4 = make_float4(b0 ? (float)(j0 + q + 0) : 0.f,
                                b1 ? (float)(j0 + q + 1) : 0.f,
                                b2 ? (float)(j0 + q + 2) : 0.f,
                                b3 ? (float)(j0 + q + 3) : 0.f);
        float4 a4 = make_float4(b0 ? 3.f : -1.f, b1 ? 3.f : -1.f,
                                b2 ? 3.f : -1.f, b3 ? 3.f : -1.f);
        *(float4*)(so + q) = s4;
        *(float4*)(dd + q) = d4;
        *(float4*)(ao + q) = a4;
    }
}

// ---------------------------------------------------------------------------
__global__ void __launch_bounds__(TPB, 1)
fused_kernel(const int* __restrict__ ei32, const float* __restrict__ attr,
             float* __restrict__ out, int E) {
    __shared__ int s_changed, s_flag;
    __shared__ uint32_t sR[NW], sExp[NW], sFr[NW];
    __shared__ int sAny;

    const int tid  = blockIdx.x * TPB + threadIdx.x;   // 0..65535
    const int lane = threadIdx.x & 31;
    const int wid  = threadIdx.x >> 5;                 // 0..15
    const int warp = tid >> 5;                         // 0..2047
    const int row  = warp;                             // rows 0..1023 active
    const int NN   = N_NODES * N_NODES;
    int bar = 0;

    if (threadIdx.x == 0) { s_changed = 0; s_flag = 1; }

    const int i64 = g_i64flag;

    // ---- P1: copy originals + scatter adj/radj + pivot ---------------------
    {
        const int stride = GRID * TPB;
        const int nloops = (E + stride - 1) / stride;
        for (int i = 0; i < nloops; i++) {           // warp-uniform trip count
            int e = tid + i * stride;
            bool v = (e < E);
            int src = 0, dst = 0; float a = 1.0f;
            if (v) {
                if (i64) { src = ei32[2 * e]; dst = ei32[2 * (E + e)]; }
                else     { src = ei32[e];     dst = ei32[E + e]; }
                a = attr[e];
                out[e] = (float)src;
                out[(E + NN) + e] = (float)dst;
                out[2 * (E + NN) + e] = a;
            }
            bool body = v && (a == 0.0f);
            if (body) {
                atomicOr(&g_adj[src * NW + (dst >> 5)], 1u << (dst & 31));
                atomicOr(&g_radj[dst * NW + (src >> 5)], 1u << (src & 31));
            }
            int cand = body ? dst : -1;
            int m = __reduce_max_sync(FULLMASK, cand);
            if (lane == 0 && m >= 0) atomicMax(&g_pivot, m);
        }
    }
    grid_sync_flag(bar++, -1, &s_changed, &s_flag);

    // ---- P2: blocks 0,1 = BFS (F fwd / B bwd); blocks 2.. = prewrite -------
    if (blockIdx.x <= 1) {
        const uint32_t* Adj = (blockIdx.x == 0) ? g_adj : g_radj;
        const int p = g_pivot;
        if (threadIdx.x < NW) { sR[threadIdx.x] = Adj[p * NW + threadIdx.x];
                                sExp[threadIdx.x] = 0u; }
        __syncthreads();
        for (int level = 0; level < N_NODES + 1; level++) {
            if (threadIdx.x == 0) sAny = 0;
            __syncthreads();
            if (threadIdx.x < NW) {
                sFr[threadIdx.x] = sR[threadIdx.x] & ~sExp[threadIdx.x];
                sExp[threadIdx.x] = sR[threadIdx.x];
                if (sFr[threadIdx.x]) sAny = 1;   // benign race, all write 1
            }
            __syncthreads();
            if (!sAny) break;
            uint32_t accum = 0;
            #pragma unroll 1
            for (int ww = wid; ww < NW; ww += 16) {   // 16 warps, 2 words each
                uint32_t bits = sFr[ww];              // warp-uniform
                const uint32_t* pk = &Adj[(ww << 10) + lane];
                while (bits) {
                    int j0 = __ffs(bits) - 1; bits &= bits - 1;
                    int j1 = j0, j2 = j0, j3 = j0;
                    int j4 = j0, j5 = j0, j6 = j0, j7 = j0;
                    if (bits) { j1 = __ffs(bits) - 1; bits &= bits - 1; }
                    if (bits) { j2 = __ffs(bits) - 1; bits &= bits - 1; }
                    if (bits) { j3 = __ffs(bits) - 1; bits &= bits - 1; }
                    if (bits) { j4 = __ffs(bits) - 1; bits &= bits - 1; }
                    if (bits) { j5 = __ffs(bits) - 1; bits &= bits - 1; }
                    if (bits) { j6 = __ffs(bits) - 1; bits &= bits - 1; }
                    if (bits) { j7 = __ffs(bits) - 1; bits &= bits - 1; }
                    uint32_t v0 = pk[j0 << 5];
                    uint32_t v1 = pk[j1 << 5];
                    uint32_t v2 = pk[j2 << 5];
                    uint32_t v3 = pk[j3 << 5];
                    uint32_t v4 = pk[j4 << 5];
                    uint32_t v5 = pk[j5 << 5];
                    uint32_t v6 = pk[j6 << 5];
                    uint32_t v7 = pk[j7 << 5];
                    accum |= (v0 | v1) | (v2 | v3) | (v4 | v5) | (v6 | v7);
                }
            }
            if (accum) atomicOr(&sR[lane], accum);
            __syncthreads();
        }
        if (threadIdx.x < NW) {
            if (blockIdx.x == 0) g_F[threadIdx.x] = sR[threadIdx.x];
            else                 g_B[threadIdx.x] = sR[threadIdx.x];
        }
    } else {
        // Prewrite the dense "all shortcut" pattern, hidden in BFS's shadow.
        int h = (blockIdx.x - 2) * TPB + threadIdx.x;       // 0..64511
        for (; h < N_NODES * NW * 2; h += (GRID - 2) * TPB)
            emit_half(out, E, h >> 1, h & 1, 0xFFFFu);
    }
    grid_sync_flag(bar++, -1, &s_changed, &s_flag);

    // ---- P3: seed + FIRST expansion fused (no barrier between) -------------
    const int p = g_pivot;
    const uint32_t Fl = g_F[lane];          // lane-resident F bitset
    const uint32_t Bl = g_B[lane];          // lane-resident B bitset
    const uint32_t pbit = (lane == (p >> 5)) ? (1u << (p & 31)) : 0u;

    uint32_t rowreg = 0, expanded = 0;
    if (row < N_NODES) {
        const int inB = (g_B[row >> 5] >> (row & 31)) & 1;
        rowreg = g_adj[(row << 5) + lane];
        if (inB) {
            // closure(row) >= F u {p}; closure(k) == F exactly for k in F&B.
            rowreg |= Fl | pbit;
            expanded = Fl & Bl;
        }
        g_R[(row << 5) + lane] = rowreg;    // publish seed (plain store)

        // First expansion using the ANALYTIC seed of other rows:
        //   seed(k) = adj[k] | (k in B ? F u {p} : 0)
        uint32_t delta = rowreg & ~expanded;
        uint32_t acc = rowreg;
        if (__any_sync(FULLMASK, delta != 0u)) {
            #pragma unroll 1
            for (int kw = 0; kw < NW; kw++) {
                uint32_t bits = __shfl_sync(FULLMASK, delta, kw);
                if (!bits) continue;
                uint32_t Bw = __shfl_sync(FULLMASK, Bl, kw);  // B word kw
                if (bits & Bw) acc |= Fl | pbit;  // any delta node in B
                const uint32_t* pk = &g_adj[(kw << 10) + lane];
                while (bits) {
                    int j0 = __ffs(bits) - 1; bits &= bits - 1;
                    int j1 = j0, j2 = j0, j3 = j0;
                    int j4 = j0, j5 = j0, j6 = j0, j7 = j0;
                    if (bits) { j1 = __ffs(bits) - 1; bits &= bits - 1; }
                    if (bits) { j2 = __ffs(bits) - 1; bits &= bits - 1; }
                    if (bits) { j3 = __ffs(bits) - 1; bits &= bits - 1; }
                    if (bits) { j4 = __ffs(bits) - 1; bits &= bits - 1; }
                    if (bits) { j5 = __ffs(bits) - 1; bits &= bits - 1; }
                    if (bits) { j6 = __ffs(bits) - 1; bits &= bits - 1; }
                    if (bits) { j7 = __ffs(bits) - 1; bits &= bits - 1; }
                    uint32_t v0 = pk[j0 << 5];
                    uint32_t v1 = pk[j1 << 5];
                    uint32_t v2 = pk[j2 << 5];
                    uint32_t v3 = pk[j3 << 5];
                    uint32_t v4 = pk[j4 << 5];
                    uint32_t v5 = pk[j5 << 5];
                    uint32_t v6 = pk[j6 << 5];
                    uint32_t v7 = pk[j7 << 5];
                    acc |= (v0 | v1) | (v2 | v3) | (v4 | v5) | (v6 | v7);
                }
            }
        }
        expanded = rowreg;
        if (__any_sync(FULLMASK, (acc & ~rowreg) != 0u)) {
            g_R[(row << 5) + lane] = acc;   // single owner: plain store
            if (lane == 0) s_changed = 1;
        }
        rowreg = acc;
    }
    int flag = grid_sync_flag(bar++, 0, &s_changed, &s_flag);

    // ---- P4: remaining expansion iterations to fixpoint --------------------
    for (int it = 1; it < MAX_ITERS && flag; it++) {
        if (row < N_NODES) {
            uint32_t delta = rowreg & ~expanded;
            uint32_t acc = rowreg;
            if (__any_sync(FULLMASK, delta != 0u)) {
                #pragma unroll 1
                for (int kw = 0; kw < NW; kw++) {
                    uint32_t bits = __shfl_sync(FULLMASK, delta, kw);
                    if (!bits) continue;
                    const uint32_t* pk = &g_R[(kw << 10) + lane];
                    while (bits) {
                        int j0 = __ffs(bits) - 1; bits &= bits - 1;
                        int j1 = j0, j2 = j0, j3 = j0;
                        int j4 = j0, j5 = j0, j6 = j0, j7 = j0;
                        if (bits) { j1 = __ffs(bits) - 1; bits &= bits - 1; }
                        if (bits) { j2 = __ffs(bits) - 1; bits &= bits - 1; }
                        if (bits) { j3 = __ffs(bits) - 1; bits &= bits - 1; }
                        if (bits) { j4 = __ffs(bits) - 1; bits &= bits - 1; }
                        if (bits) { j5 = __ffs(bits) - 1; bits &= bits - 1; }
                        if (bits) { j6 = __ffs(bits) - 1; bits &= bits - 1; }
                        if (bits) { j7 = __ffs(bits) - 1; bits &= bits - 1; }
                        uint32_t v0 = pk[j0 << 5];
                        uint32_t v1 = pk[j1 << 5];
                        uint32_t v2 = pk[j2 << 5];
                        uint32_t v3 = pk[j3 << 5];
                        uint32_t v4 = pk[j4 << 5];
                        uint32_t v5 = pk[j5 << 5];
                        uint32_t v6 = pk[j6 << 5];
                        uint32_t v7 = pk[j7 << 5];
                        acc |= (v0 | v1) | (v2 | v3) | (v4 | v5) | (v6 | v7);
                    }
                }
            }
            expanded = rowreg;
            if (__any_sync(FULLMASK, (acc & ~rowreg) != 0u)) {
                g_R[(row << 5) + lane] = acc;
                if (lane == 0) s_changed = 1;
            }
            rowreg = acc;
        }
        flag = grid_sync_flag(bar++, it, &s_changed, &s_flag);
    }

    // ---- P5: emit fix-up (only halves of words that differ from prewrite) --
    {
        int w = tid >> 1;                   // 65536 threads, half-word each
        int half = tid & 1;
        uint32_t sc = g_R[w] & ~g_adj[w];
        if (sc != FULLMASK)
            emit_half(out, E, w, half, (sc >> (half << 4)) & 0xFFFFu);
    }
}

// ---------------------------------------------------------------------------
extern "C" void kernel_launch(void* const* d_in, const int* in_sizes, int n_in,
                              void* d_out, int out_size) {
    const int* ei = (const int*)d_in[0];
    const float* attr = (const float*)d_in[1];
    float* out = (float*)d_out;
    int E = in_sizes[1];

    init_kernel<<<64, 512>>>(ei);
    fused_kernel<<<GRID, TPB>>>(ei, attr, out, E);
}